// round 7
// baseline (speedup 1.0000x reference)
#include <cuda_runtime.h>

#define BB 4
#define NN 20000
#define EE 320000
#define INDIM 21
#define ED 64
#define H2 128
#define LL 3
#define BN_EPS 1e-5f

// ---------------- scratch (device globals; no allocations) ----------------
__device__ __align__(16) float g_H[BB * NN * ED];    // current node embeddings
__device__ __align__(16) float g_A1[BB * NN * ED];   // scattered neighbor feature sums
__device__ __align__(16) float g_P[BB * NN * H2];    // pre-BN hidden activations
__device__ float g_deg[BB * NN];          // in-degree per node
__device__ float g_s[BB * NN];            // sum of edge_attr per dst node
__device__ float g_stats[BB * 2 * H2];    // per-(graph,channel) sum / sumsq
__device__ float g_scale[BB * H2];        // rstd * gamma
__device__ float g_shift[BB * H2];        // beta - mean * rstd * gamma
__device__ float g_uv[2 * H2];            // u = edgeW@W1_bot, v = edgeb@W1_bot
__device__ __align__(8) int2 g_ei32[BB * EE];        // packed (src, dst) int32
__device__ int g_is64;                    // 1 if edge_index buffer is int64

// ---------------- dtype detection for edge_index ----------------
// If the buffer is int64 (values < 20000), every odd int32 word (the high half)
// is zero. If it is int32, odd words are real node ids (P(all zero) ~ 0).
__global__ void k_detect(const int* __restrict__ v) {
    __shared__ int nz[256];
    int t = threadIdx.x;
    nz[t] = v[2 * t + 1];
    __syncthreads();
    for (int s = 128; s > 0; s >>= 1) {
        if (t < s) nz[t] |= nz[t + s];
        __syncthreads();
    }
    if (t == 0) g_is64 = (nz[0] == 0) ? 1 : 0;
}

// ---------------- zero kernels ----------------
__global__ void k_zero_pass() {
    int i = blockIdx.x * blockDim.x + threadIdx.x;
    if (i < BB * NN) { g_deg[i] = 0.0f; g_s[i] = 0.0f; }
}

__global__ void k_zero_layer() {
    int i = blockIdx.x * blockDim.x + threadIdx.x;
    if (i < BB * NN * ED / 4)
        reinterpret_cast<float4*>(g_A1)[i] = make_float4(0.f, 0.f, 0.f, 0.f);
    if (i < BB * 2 * H2) g_stats[i] = 0.0f;
}

// ---------------- degree / edge-scalar scatter + edge-index repack ----------------
__global__ void k_degs(const void* __restrict__ ei, const float* __restrict__ eattr) {
    int gid = blockIdx.x * blockDim.x + threadIdx.x;
    if (gid >= BB * EE) return;
    int b = gid / EE, e = gid - b * EE;
    int src, dst;
    if (g_is64) {
        const long long* e64 = (const long long*)ei;
        src = (int)e64[(long long)b * 2 * EE + e];
        dst = (int)e64[(long long)b * 2 * EE + EE + e];
    } else {
        const int* e32 = (const int*)ei;
        src = e32[b * 2 * EE + e];
        dst = e32[b * 2 * EE + EE + e];
    }
    // defensive clamp: never trap; wrongness would surface as rel_err instead
    src = (src < 0) ? 0 : (src >= NN ? NN - 1 : src);
    dst = (dst < 0) ? 0 : (dst >= NN ? NN - 1 : dst);
    g_ei32[gid] = make_int2(src, dst);
    atomicAdd(&g_deg[b * NN + dst], 1.0f);
    atomicAdd(&g_s[b * NN + dst], eattr[gid]);
}

// ---------------- input embedding: h = x @ inW + inb ----------------
__global__ void k_embed(const float* __restrict__ x, const float* __restrict__ inW,
                        const float* __restrict__ inb) {
    __shared__ float Wsh[INDIM * ED];
    __shared__ float xs[4][INDIM];
    int tid = threadIdx.x;                       // 256
    for (int i = tid; i < INDIM * ED; i += 256) Wsh[i] = inW[i];
    int row0 = blockIdx.x * 4;                   // flattened (b,n) row
    for (int i = tid; i < 4 * INDIM; i += 256) {
        int r = i / INDIM, k = i - r * INDIM;
        xs[r][k] = x[(long long)(row0 + r) * INDIM + k];
    }
    __syncthreads();
    int r = tid >> 6;
    int c = tid & 63;
    float acc = inb[c];
#pragma unroll
    for (int k = 0; k < INDIM; k++) acc += xs[r][k] * Wsh[k * ED + c];
    g_H[(long long)(row0 + r) * ED + c] = acc;
}

// ---------------- neighbor-feature scatter: A1[dst] += h[src] ----------------
// Each edge uses 16 lanes; lane i handles channels {i, i+16, i+32, i+48}.
// The 64B stride between a single thread's atomics prevents vector-RED fusion,
// while lanes 0..15 still cover contiguous 64B segments for coalescing.
__global__ void k_scatter() {
    int gid = blockIdx.x * blockDim.x + threadIdx.x;   // BB*EE*16 threads
    int lane = gid & 15;
    int es = gid >> 4;                                 // global edge slot
    if (es >= BB * EE) return;
    int2 sd = g_ei32[es];                              // warp-coalesced (2 distinct per warp)
    int b = es / EE;
    const float* hs = &g_H[((long long)(b * NN + sd.x)) * ED];
    float* p = &g_A1[((long long)(b * NN + sd.y)) * ED];
    float v0 = hs[lane +  0];
    float v1 = hs[lane + 16];
    float v2 = hs[lane + 32];
    float v3 = hs[lane + 48];
    atomicAdd(p + lane +  0, v0);
    atomicAdd(p + lane + 16, v1);
    atomicAdd(p + lane + 32, v2);
    atomicAdd(p + lane + 48, v3);
}

// ---------------- per-layer rank-1 terms u,v ----------------
__global__ void k_uv(const float* __restrict__ edgeW, const float* __restrict__ edgeb,
                     const float* __restrict__ W1, int l) {
    int c = threadIdx.x;   // 128
    float u = 0.f, v = 0.f;
#pragma unroll
    for (int k = 0; k < ED; k++) {
        float w1 = W1[((long long)l * H2 + ED + k) * H2 + c];
        u += edgeW[l * ED + k] * w1;
        v += edgeb[l * ED + k] * w1;
    }
    g_uv[c] = u;
    g_uv[H2 + c] = v;
}

// ---------------- GEMM1: P = A1 @ W1_top + b1 + s*u + deg*v, + BN stats ----------------
__global__ void __launch_bounds__(128) k_gemm1(const float* __restrict__ W1,
                                               const float* __restrict__ b1, int l) {
    __shared__ float Wsh[ED * H2];       // 32 KB, [k][c]
    __shared__ float ash[16 * ED];       // 16 rows of A1
    __shared__ float red[4][2 * H2];     // cross-warp stat reduction
    int tid = threadIdx.x;               // 128
    int b = blockIdx.x;
    int n0 = blockIdx.y * 16;

    for (int i = tid; i < ED * H2; i += 128) Wsh[i] = W1[(long long)l * H2 * H2 + i];
    const float* A1b = g_A1 + ((long long)(b * NN + n0)) * ED;
    for (int i = tid; i < 16 * ED; i += 128) ash[i] = A1b[i];
    __syncthreads();

    int ry = tid >> 5;    // warp id: 4 row-groups (rows ry*4..ry*4+3)
    int cx = tid & 31;    // 4 consecutive channels per thread

    float uc[4], vc[4], b1c[4];
#pragma unroll
    for (int j = 0; j < 4; j++) {
        int c = cx * 4 + j;
        uc[j] = g_uv[c];
        vc[j] = g_uv[H2 + c];
        b1c[j] = b1[l * H2 + c];
    }
    float acc[4][4];
#pragma unroll
    for (int i = 0; i < 4; i++) {
        int n = n0 + ry * 4 + i;
        float sv = g_s[b * NN + n];
        float dv = g_deg[b * NN + n];
#pragma unroll
        for (int j = 0; j < 4; j++) acc[i][j] = b1c[j] + sv * uc[j] + dv * vc[j];
    }

#pragma unroll 8
    for (int k = 0; k < ED; k++) {
        float4 w = *reinterpret_cast<const float4*>(&Wsh[k * H2 + cx * 4]);
        float a0 = ash[(ry * 4 + 0) * ED + k];
        float a1 = ash[(ry * 4 + 1) * ED + k];
        float a2 = ash[(ry * 4 + 2) * ED + k];
        float a3 = ash[(ry * 4 + 3) * ED + k];
        acc[0][0] += a0 * w.x; acc[0][1] += a0 * w.y; acc[0][2] += a0 * w.z; acc[0][3] += a0 * w.w;
        acc[1][0] += a1 * w.x; acc[1][1] += a1 * w.y; acc[1][2] += a1 * w.z; acc[1][3] += a1 * w.w;
        acc[2][0] += a2 * w.x; acc[2][1] += a2 * w.y; acc[2][2] += a2 * w.z; acc[2][3] += a2 * w.w;
        acc[3][0] += a3 * w.x; acc[3][1] += a3 * w.y; acc[3][2] += a3 * w.z; acc[3][3] += a3 * w.w;
    }

    float sc[4] = {0.f, 0.f, 0.f, 0.f};
    float sq[4] = {0.f, 0.f, 0.f, 0.f};
#pragma unroll
    for (int i = 0; i < 4; i++) {
        int n = n0 + ry * 4 + i;
        float4 o = make_float4(acc[i][0], acc[i][1], acc[i][2], acc[i][3]);
        *reinterpret_cast<float4*>(&g_P[((long long)(b * NN + n)) * H2 + cx * 4]) = o;
#pragma unroll
        for (int j = 0; j < 4; j++) { sc[j] += acc[i][j]; sq[j] += acc[i][j] * acc[i][j]; }
    }
#pragma unroll
    for (int j = 0; j < 4; j++) {
        red[ry][cx * 4 + j] = sc[j];
        red[ry][H2 + cx * 4 + j] = sq[j];
    }
    __syncthreads();
    // stride-512B between this thread's two atomics -> cannot be vector-fused
    for (int i = tid; i < 2 * H2; i += 128) {
        float t = red[0][i] + red[1][i] + red[2][i] + red[3][i];
        atomicAdd(&g_stats[b * 2 * H2 + i], t);
    }
}

// ---------------- finalize BN coefficients ----------------
__global__ void k_stats(const float* __restrict__ gamma, const float* __restrict__ beta, int l) {
    int b = blockIdx.x;
    int c = threadIdx.x;   // 128
    float sum = g_stats[b * 2 * H2 + c];
    float sq  = g_stats[b * 2 * H2 + H2 + c];
    float m = sum / (float)NN;
    float var = sq / (float)NN - m * m;
    float rstd = rsqrtf(var + BN_EPS);
    float scv = rstd * gamma[l * H2 + c];
    g_scale[b * H2 + c] = scv;
    g_shift[b * H2 + c] = beta[l * H2 + c] - m * scv;
}

// ---------------- GEMM2: h' = relu(BN(P)) @ W2 + b2 (+ inter-layer relu) ----------------
__global__ void __launch_bounds__(128) k_gemm2(const float* __restrict__ W2,
                                               const float* __restrict__ b2,
                                               float* __restrict__ out, int l, int writeOut) {
    __shared__ float Wsh[H2 * ED];     // 32 KB, [k][c]
    __shared__ float qsh[32 * H2];     // 16 KB, 32 normalized rows
    int tid = threadIdx.x;             // 128
    int b = blockIdx.x;
    int n0 = blockIdx.y * 32;

    for (int i = tid; i < H2 * ED; i += 128) Wsh[i] = W2[(long long)l * H2 * ED + i];
    float scl = g_scale[b * H2 + tid];
    float shf = g_shift[b * H2 + tid];
    const float* Pb = g_P + ((long long)(b * NN + n0)) * H2;
#pragma unroll 4
    for (int r = 0; r < 32; r++) {
        float p = Pb[r * H2 + tid];
        float q = p * scl + shf;
        qsh[r * H2 + tid] = q > 0.f ? q : 0.f;
    }
    __syncthreads();

    int ry = tid >> 4;   // 8 row-groups of 4 rows
    int cx = tid & 15;   // 4 consecutive output channels per thread
    float acc[4][4];
#pragma unroll
    for (int i = 0; i < 4; i++)
#pragma unroll
        for (int j = 0; j < 4; j++) acc[i][j] = b2[l * ED + cx * 4 + j];

#pragma unroll 8
    for (int k = 0; k < H2; k++) {
        float4 w = *reinterpret_cast<const float4*>(&Wsh[k * ED + cx * 4]);
        float a0 = qsh[(ry * 4 + 0) * H2 + k];
        float a1 = qsh[(ry * 4 + 1) * H2 + k];
        float a2 = qsh[(ry * 4 + 2) * H2 + k];
        float a3 = qsh[(ry * 4 + 3) * H2 + k];
        acc[0][0] += a0 * w.x; acc[0][1] += a0 * w.y; acc[0][2] += a0 * w.z; acc[0][3] += a0 * w.w;
        acc[1][0] += a1 * w.x; acc[1][1] += a1 * w.y; acc[1][2] += a1 * w.z; acc[1][3] += a1 * w.w;
        acc[2][0] += a2 * w.x; acc[2][1] += a2 * w.y; acc[2][2] += a2 * w.z; acc[2][3] += a2 * w.w;
        acc[3][0] += a3 * w.x; acc[3][1] += a3 * w.y; acc[3][2] += a3 * w.z; acc[3][3] += a3 * w.w;
    }

#pragma unroll
    for (int i = 0; i < 4; i++) {
        int n = n0 + ry * 4 + i;
        float4 o;
        if (writeOut) {
            o = make_float4(acc[i][0], acc[i][1], acc[i][2], acc[i][3]);
            *reinterpret_cast<float4*>(&out[((long long)(b * NN + n)) * ED + cx * 4]) = o;
        } else {
            o = make_float4(acc[i][0] > 0.f ? acc[i][0] : 0.f,
                            acc[i][1] > 0.f ? acc[i][1] : 0.f,
                            acc[i][2] > 0.f ? acc[i][2] : 0.f,
                            acc[i][3] > 0.f ? acc[i][3] : 0.f);
            *reinterpret_cast<float4*>(&g_H[((long long)(b * NN + n)) * ED + cx * 4]) = o;
        }
    }
}

// ---------------- launcher ----------------
extern "C" void kernel_launch(void* const* d_in, const int* in_sizes, int n_in,
                              void* d_out, int out_size) {
    const float*     x      = (const float*)d_in[0];
    const void*      ei     = (const void*)d_in[1];   // int32 or int64, auto-detected
    const float*     eattr  = (const float*)d_in[2];
    const float*     inW    = (const float*)d_in[3];
    const float*     inb    = (const float*)d_in[4];
    const float*     edgeW  = (const float*)d_in[5];
    const float*     edgeb  = (const float*)d_in[6];
    const float*     W1     = (const float*)d_in[7];
    const float*     b1     = (const float*)d_in[8];
    const float*     gamma  = (const float*)d_in[9];
    const float*     beta   = (const float*)d_in[10];
    const float*     W2     = (const float*)d_in[11];
    const float*     b2     = (const float*)d_in[12];
    float* out = (float*)d_out;

    k_detect<<<1, 256>>>((const int*)ei);
    k_zero_pass<<<(BB * NN + 255) / 256, 256>>>();
    k_degs<<<(BB * EE + 255) / 256, 256>>>(ei, eattr);
    k_embed<<<BB * NN / 4, 256>>>(x, inW, inb);

    for (int l = 0; l < LL; l++) {
        k_zero_layer<<<(BB * NN * ED / 4 + 255) / 256, 256>>>();
        k_scatter<<<BB * EE * 16 / 256, 256>>>();
        k_uv<<<1, 128>>>(edgeW, edgeb, W1, l);
        k_gemm1<<<dim3(BB, NN / 16), 128>>>(W1, b1, l);
        k_stats<<<BB, 128>>>(gamma, beta, l);
        k_gemm2<<<dim3(BB, NN / 32), 128>>>(W2, b2, out, l, (l == LL - 1) ? 1 : 0);
    }
}

// round 9
// speedup vs baseline: 1.1841x; 1.1841x over previous
#include <cuda_runtime.h>

#define BB 4
#define NN 20000
#define EE 320000
#define INDIM 21
#define ED 64
#define H2 128
#define LL 3
#define BN_EPS 1e-5f

// ---------------- scratch (device globals; no allocations) ----------------
__device__ __align__(16) float g_H[BB * NN * ED];    // current node embeddings
__device__ __align__(16) float g_A1[BB * NN * ED];   // gathered neighbor feature sums
__device__ __align__(16) float g_P[BB * NN * H2];    // pre-BN hidden activations
__device__ float g_deg[BB * NN];          // in-degree per node (float, exact small ints)
__device__ float g_s[BB * NN];            // sum of edge_attr per dst node
__device__ float g_stats[BB * 2 * H2];    // per-(graph,channel) sum / sumsq
__device__ float g_scale[BB * H2];        // rstd * gamma
__device__ float g_shift[BB * H2];        // beta - mean * rstd * gamma
__device__ float g_uv[2 * H2];            // u = edgeW@W1_bot, v = edgeb@W1_bot
__device__ __align__(8) int2 g_ei32[BB * EE];        // packed (src, dst) int32
__device__ int g_rowptr[BB * NN];         // CSR row offsets (within batch)
__device__ int g_fill[BB * NN];           // insertion cursors
__device__ int g_csr[BB * EE];            // src ids grouped by dst
__device__ int g_is64;                    // 1 if edge_index buffer is int64

// ---------------- dtype detection for edge_index ----------------
__global__ void k_detect(const int* __restrict__ v) {
    __shared__ int nz[256];
    int t = threadIdx.x;
    nz[t] = v[2 * t + 1];
    __syncthreads();
    for (int s = 128; s > 0; s >>= 1) {
        if (t < s) nz[t] |= nz[t + s];
        __syncthreads();
    }
    if (t == 0) g_is64 = (nz[0] == 0) ? 1 : 0;
}

__global__ void k_zero_pass() {
    int i = blockIdx.x * blockDim.x + threadIdx.x;
    if (i < BB * NN) { g_deg[i] = 0.0f; g_s[i] = 0.0f; }
}

// ---------------- degree / edge-scalar scatter + edge-index repack ----------------
__global__ void k_degs(const void* __restrict__ ei, const float* __restrict__ eattr) {
    int gid = blockIdx.x * blockDim.x + threadIdx.x;
    if (gid >= BB * EE) return;
    int b = gid / EE, e = gid - b * EE;
    int src, dst;
    if (g_is64) {
        const long long* e64 = (const long long*)ei;
        src = (int)e64[(long long)b * 2 * EE + e];
        dst = (int)e64[(long long)b * 2 * EE + EE + e];
    } else {
        const int* e32 = (const int*)ei;
        src = e32[b * 2 * EE + e];
        dst = e32[b * 2 * EE + EE + e];
    }
    src = (src < 0) ? 0 : (src >= NN ? NN - 1 : src);
    dst = (dst < 0) ? 0 : (dst >= NN ? NN - 1 : dst);
    g_ei32[gid] = make_int2(src, dst);
    atomicAdd(&g_deg[b * NN + dst], 1.0f);
    atomicAdd(&g_s[b * NN + dst], eattr[gid]);
}

// ---------------- CSR rowptr: per-batch exclusive scan of degrees ----------------
__global__ void k_scan() {          // one block per batch, 256 threads
    __shared__ int ts[256];
    int b = blockIdx.x;
    int t = threadIdx.x;
    const int CH = (NN + 255) / 256;     // 79
    int lo = t * CH, hi = lo + CH;
    if (hi > NN) hi = NN;
    int sum = 0;
    for (int n = lo; n < hi; n++) sum += (int)g_deg[b * NN + n];
    ts[t] = sum;
    __syncthreads();
    // Hillis-Steele inclusive scan
    for (int off = 1; off < 256; off <<= 1) {
        int v = (t >= off) ? ts[t - off] : 0;
        __syncthreads();
        ts[t] += v;
        __syncthreads();
    }
    int run = (t == 0) ? 0 : ts[t - 1];  // exclusive prefix
    for (int n = lo; n < hi; n++) {
        g_rowptr[b * NN + n] = run;
        g_fill[b * NN + n] = run;
        run += (int)g_deg[b * NN + n];
    }
}

// ---------------- CSR fill: bucket src ids by dst ----------------
__global__ void k_fill() {
    int gid = blockIdx.x * blockDim.x + threadIdx.x;
    if (gid >= BB * EE) return;
    int b = gid / EE;
    int2 sd = g_ei32[gid];
    int pos = atomicAdd(&g_fill[b * NN + sd.y], 1);
    g_csr[b * EE + pos] = sd.x;
}

// ---------------- input embedding: h = x @ inW + inb ----------------
__global__ void __launch_bounds__(256) k_embed(const float* __restrict__ x,
                                               const float* __restrict__ inW,
                                               const float* __restrict__ inb) {
    __shared__ __align__(16) float Wsh[INDIM * ED];
    __shared__ float xs[16][INDIM];
    int tid = threadIdx.x;                       // 256
    for (int i = tid; i < INDIM * ED; i += 256) Wsh[i] = inW[i];
    int row0 = blockIdx.x * 16;                  // flattened (b,n) row
    for (int i = tid; i < 16 * INDIM; i += 256) {
        int r = i / INDIM, k = i - r * INDIM;
        xs[r][k] = x[(long long)(row0 + r) * INDIM + k];
    }
    __syncthreads();
    int r = tid >> 4;      // 16 rows
    int c4 = tid & 15;     // 4 channels per thread
    float4 acc = *reinterpret_cast<const float4*>(&inb[c4 * 4]);
#pragma unroll
    for (int k = 0; k < INDIM; k++) {
        float xv = xs[r][k];
        float4 w = *reinterpret_cast<const float4*>(&Wsh[k * ED + c4 * 4]);
        acc.x += xv * w.x; acc.y += xv * w.y; acc.z += xv * w.z; acc.w += xv * w.w;
    }
    *reinterpret_cast<float4*>(&g_H[(long long)(row0 + r) * ED + c4 * 4]) = acc;
}

// ---------------- CSR gather: A1[n] = sum over in-edges of h[src] ----------------
// One warp per destination node. Lanes split: half = lane>>4 handles every 2nd
// edge; 16 lanes x float4 cover the 64-channel row. No atomics, full overwrite.
__global__ void __launch_bounds__(256) k_gather() {
    int gw = (blockIdx.x * blockDim.x + threadIdx.x) >> 5;   // global warp = node
    if (gw >= BB * NN) return;
    int b = gw / NN, n = gw - b * NN;
    int lane = threadIdx.x & 31;
    int half = lane >> 4, c4 = lane & 15;
    int start = g_rowptr[b * NN + n];
    int end = start + (int)g_deg[b * NN + n];
    const int* csr = g_csr + b * EE;
    const float* Hb = g_H + (long long)b * NN * ED;
    float4 a0 = make_float4(0.f, 0.f, 0.f, 0.f);
    float4 a1 = make_float4(0.f, 0.f, 0.f, 0.f);
    int e = start + half;
    for (; e + 2 < end; e += 4) {
        int s0 = csr[e];
        int s1 = csr[e + 2];
        float4 v0 = *reinterpret_cast<const float4*>(&Hb[(long long)s0 * ED + c4 * 4]);
        float4 v1 = *reinterpret_cast<const float4*>(&Hb[(long long)s1 * ED + c4 * 4]);
        a0.x += v0.x; a0.y += v0.y; a0.z += v0.z; a0.w += v0.w;
        a1.x += v1.x; a1.y += v1.y; a1.z += v1.z; a1.w += v1.w;
    }
    if (e < end) {
        int s0 = csr[e];
        float4 v0 = *reinterpret_cast<const float4*>(&Hb[(long long)s0 * ED + c4 * 4]);
        a0.x += v0.x; a0.y += v0.y; a0.z += v0.z; a0.w += v0.w;
    }
    a0.x += a1.x; a0.y += a1.y; a0.z += a1.z; a0.w += a1.w;
    // combine the two 16-lane halves
    a0.x += __shfl_xor_sync(0xffffffffu, a0.x, 16);
    a0.y += __shfl_xor_sync(0xffffffffu, a0.y, 16);
    a0.z += __shfl_xor_sync(0xffffffffu, a0.z, 16);
    a0.w += __shfl_xor_sync(0xffffffffu, a0.w, 16);
    if (half == 0)
        *reinterpret_cast<float4*>(&g_A1[((long long)(b * NN + n)) * ED + c4 * 4]) = a0;
}

// ---------------- per-layer rank-1 terms u,v (+ zero BN stats) ----------------
__global__ void k_uv(const float* __restrict__ edgeW, const float* __restrict__ edgeb,
                     const float* __restrict__ W1, int l) {
    int c = threadIdx.x;   // 128
    for (int i = c; i < BB * 2 * H2; i += 128) g_stats[i] = 0.0f;
    float u = 0.f, v = 0.f;
#pragma unroll
    for (int k = 0; k < ED; k++) {
        float w1 = W1[((long long)l * H2 + ED + k) * H2 + c];
        u += edgeW[l * ED + k] * w1;
        v += edgeb[l * ED + k] * w1;
    }
    g_uv[c] = u;
    g_uv[H2 + c] = v;
}

// ---------------- GEMM1: P = A1 @ W1_top + b1 + s*u + deg*v, + BN stats ----------------
__global__ void __launch_bounds__(128) k_gemm1(const float* __restrict__ W1,
                                               const float* __restrict__ b1, int l) {
    __shared__ __align__(16) float Wsh[ED * H2];   // 32 KB, [k][c]
    __shared__ __align__(16) float ash[16 * ED];   // 16 rows of A1
    __shared__ float red[4][2 * H2];               // cross-warp stat reduction
    int tid = threadIdx.x;               // 128
    int b = blockIdx.x;
    int n0 = blockIdx.y * 16;

    for (int i = tid; i < ED * H2; i += 128) Wsh[i] = W1[(long long)l * H2 * H2 + i];
    const float* A1b = g_A1 + ((long long)(b * NN + n0)) * ED;
    for (int i = tid; i < 16 * ED; i += 128) ash[i] = A1b[i];
    __syncthreads();

    int ry = tid >> 5;    // warp id: 4 row-groups
    int cx = tid & 31;    // 4 consecutive channels per thread

    float uc[4], vc[4], b1c[4];
#pragma unroll
    for (int j = 0; j < 4; j++) {
        int c = cx * 4 + j;
        uc[j] = g_uv[c];
        vc[j] = g_uv[H2 + c];
        b1c[j] = b1[l * H2 + c];
    }
    float acc[4][4];
#pragma unroll
    for (int i = 0; i < 4; i++) {
        int n = n0 + ry * 4 + i;
        float sv = g_s[b * NN + n];
        float dv = g_deg[b * NN + n];
#pragma unroll
        for (int j = 0; j < 4; j++) acc[i][j] = b1c[j] + sv * uc[j] + dv * vc[j];
    }

#pragma unroll 8
    for (int k = 0; k < ED; k++) {
        float4 w = *reinterpret_cast<const float4*>(&Wsh[k * H2 + cx * 4]);
        float a0 = ash[(ry * 4 + 0) * ED + k];
        float a1 = ash[(ry * 4 + 1) * ED + k];
        float a2 = ash[(ry * 4 + 2) * ED + k];
        float a3 = ash[(ry * 4 + 3) * ED + k];
        acc[0][0] += a0 * w.x; acc[0][1] += a0 * w.y; acc[0][2] += a0 * w.z; acc[0][3] += a0 * w.w;
        acc[1][0] += a1 * w.x; acc[1][1] += a1 * w.y; acc[1][2] += a1 * w.z; acc[1][3] += a1 * w.w;
        acc[2][0] += a2 * w.x; acc[2][1] += a2 * w.y; acc[2][2] += a2 * w.z; acc[2][3] += a2 * w.w;
        acc[3][0] += a3 * w.x; acc[3][1] += a3 * w.y; acc[3][2] += a3 * w.z; acc[3][3] += a3 * w.w;
    }

    float sc[4] = {0.f, 0.f, 0.f, 0.f};
    float sq[4] = {0.f, 0.f, 0.f, 0.f};
#pragma unroll
    for (int i = 0; i < 4; i++) {
        int n = n0 + ry * 4 + i;
        float4 o = make_float4(acc[i][0], acc[i][1], acc[i][2], acc[i][3]);
        *reinterpret_cast<float4*>(&g_P[((long long)(b * NN + n)) * H2 + cx * 4]) = o;
#pragma unroll
        for (int j = 0; j < 4; j++) { sc[j] += acc[i][j]; sq[j] += acc[i][j] * acc[i][j]; }
    }
#pragma unroll
    for (int j = 0; j < 4; j++) {
        red[ry][cx * 4 + j] = sc[j];
        red[ry][H2 + cx * 4 + j] = sq[j];
    }
    __syncthreads();
    for (int i = tid; i < 2 * H2; i += 128) {
        float t = red[0][i] + red[1][i] + red[2][i] + red[3][i];
        atomicAdd(&g_stats[b * 2 * H2 + i], t);
    }
}

// ---------------- finalize BN coefficients ----------------
__global__ void k_stats(const float* __restrict__ gamma, const float* __restrict__ beta, int l) {
    int b = blockIdx.x;
    int c = threadIdx.x;   // 128
    float sum = g_stats[b * 2 * H2 + c];
    float sq  = g_stats[b * 2 * H2 + H2 + c];
    float m = sum / (float)NN;
    float var = sq / (float)NN - m * m;
    float rstd = rsqrtf(var + BN_EPS);
    float scv = rstd * gamma[l * H2 + c];
    g_scale[b * H2 + c] = scv;
    g_shift[b * H2 + c] = beta[l * H2 + c] - m * scv;
}

// ---------------- GEMM2: h' = relu(BN(P)) @ W2 + b2 (+ inter-layer relu) ----------------
__global__ void __launch_bounds__(128) k_gemm2(const float* __restrict__ W2,
                                               const float* __restrict__ b2,
                                               float* __restrict__ out, int l, int writeOut) {
    __shared__ __align__(16) float Wsh[H2 * ED];   // 32 KB, [k][c]
    __shared__ __align__(16) float qsh[32 * H2];   // 16 KB, 32 normalized rows
    int tid = threadIdx.x;             // 128
    int b = blockIdx.x;
    int n0 = blockIdx.y * 32;

    for (int i = tid; i < H2 * ED; i += 128) Wsh[i] = W2[(long long)l * H2 * ED + i];
    float scl = g_scale[b * H2 + tid];
    float shf = g_shift[b * H2 + tid];
    const float* Pb = g_P + ((long long)(b * NN + n0)) * H2;
#pragma unroll 4
    for (int r = 0; r < 32; r++) {
        float p = Pb[r * H2 + tid];
        float q = p * scl + shf;
        qsh[r * H2 + tid] = q > 0.f ? q : 0.f;
    }
    __syncthreads();

    int ry = tid >> 4;   // 8 row-groups of 4 rows
    int cx = tid & 15;   // 4 consecutive output channels per thread
    float acc[4][4];
#pragma unroll
    for (int i = 0; i < 4; i++)
#pragma unroll
        for (int j = 0; j < 4; j++) acc[i][j] = b2[l * ED + cx * 4 + j];

#pragma unroll 8
    for (int k = 0; k < H2; k++) {
        float4 w = *reinterpret_cast<const float4*>(&Wsh[k * ED + cx * 4]);
        float a0 = qsh[(ry * 4 + 0) * H2 + k];
        float a1 = qsh[(ry * 4 + 1) * H2 + k];
        float a2 = qsh[(ry * 4 + 2) * H2 + k];
        float a3 = qsh[(ry * 4 + 3) * H2 + k];
        acc[0][0] += a0 * w.x; acc[0][1] += a0 * w.y; acc[0][2] += a0 * w.z; acc[0][3] += a0 * w.w;
        acc[1][0] += a1 * w.x; acc[1][1] += a1 * w.y; acc[1][2] += a1 * w.z; acc[1][3] += a1 * w.w;
        acc[2][0] += a2 * w.x; acc[2][1] += a2 * w.y; acc[2][2] += a2 * w.z; acc[2][3] += a2 * w.w;
        acc[3][0] += a3 * w.x; acc[3][1] += a3 * w.y; acc[3][2] += a3 * w.z; acc[3][3] += a3 * w.w;
    }

#pragma unroll
    for (int i = 0; i < 4; i++) {
        int n = n0 + ry * 4 + i;
        float4 o;
        if (writeOut) {
            o = make_float4(acc[i][0], acc[i][1], acc[i][2], acc[i][3]);
            *reinterpret_cast<float4*>(&out[((long long)(b * NN + n)) * ED + cx * 4]) = o;
        } else {
            o = make_float4(acc[i][0] > 0.f ? acc[i][0] : 0.f,
                            acc[i][1] > 0.f ? acc[i][1] : 0.f,
                            acc[i][2] > 0.f ? acc[i][2] : 0.f,
                            acc[i][3] > 0.f ? acc[i][3] : 0.f);
            *reinterpret_cast<float4*>(&g_H[((long long)(b * NN + n)) * ED + cx * 4]) = o;
        }
    }
}

// ---------------- launcher ----------------
extern "C" void kernel_launch(void* const* d_in, const int* in_sizes, int n_in,
                              void* d_out, int out_size) {
    const float*     x      = (const float*)d_in[0];
    const void*      ei     = (const void*)d_in[1];   // int32 or int64, auto-detected
    const float*     eattr  = (const float*)d_in[2];
    const float*     inW    = (const float*)d_in[3];
    const float*     inb    = (const float*)d_in[4];
    const float*     edgeW  = (const float*)d_in[5];
    const float*     edgeb  = (const float*)d_in[6];
    const float*     W1     = (const float*)d_in[7];
    const float*     b1     = (const float*)d_in[8];
    const float*     gamma  = (const float*)d_in[9];
    const float*     beta   = (const float*)d_in[10];
    const float*     W2     = (const float*)d_in[11];
    const float*     b2     = (const float*)d_in[12];
    float* out = (float*)d_out;

    k_detect<<<1, 256>>>((const int*)ei);
    k_zero_pass<<<(BB * NN + 255) / 256, 256>>>();
    k_degs<<<(BB * EE + 255) / 256, 256>>>(ei, eattr);
    k_scan<<<BB, 256>>>();
    k_fill<<<(BB * EE + 255) / 256, 256>>>();
    k_embed<<<BB * NN / 16, 256>>>(x, inW, inb);

    for (int l = 0; l < LL; l++) {
        k_gather<<<(BB * NN * 32 + 255) / 256, 256>>>();
        k_uv<<<1, 128>>>(edgeW, edgeb, W1, l);
        k_gemm1<<<dim3(BB, NN / 16), 128>>>(W1, b1, l);
        k_stats<<<BB, 128>>>(gamma, beta, l);
        k_gemm2<<<dim3(BB, NN / 32), 128>>>(W2, b2, out, l, (l == LL - 1) ? 1 : 0);
    }
}

// round 12
// speedup vs baseline: 1.3783x; 1.1640x over previous
#include <cuda_runtime.h>

#define BB 4
#define NN 20000
#define EE 320000
#define INDIM 21
#define ED 64
#define H2 128
#define LL 3
#define BN_EPS 1e-5f
#define SCB 79              // scan blocks per batch (79*256 >= 20000)

// ---------------- scratch (device globals; no allocations) ----------------
__device__ __align__(16) float g_H[BB * NN * ED];    // current node embeddings
__device__ __align__(16) float g_A1[BB * NN * ED];   // gathered neighbor feature sums
__device__ __align__(16) float g_P[BB * NN * H2];    // pre-BN hidden activations
__device__ float g_deg[BB * NN];          // in-degree per node
__device__ float g_s[BB * NN];            // sum of edge_attr per dst node
__device__ float g_stats[LL * BB * 2 * H2];  // per-(layer,graph,channel) sum / sumsq
__device__ float g_uv[LL * 2 * H2];       // per-layer u,v rank-1 terms
__device__ __align__(8) int2 g_ei32[BB * EE];        // packed (src, dst) int32
__device__ int g_rowptr[BB * NN];         // CSR row offsets (within batch)
__device__ int g_fill[BB * NN];           // insertion cursors
__device__ int g_csr[BB * EE];            // src ids grouped by dst
__device__ int g_bsum[BB * SCB];          // scan partials
__device__ int g_is64;                    // 1 if edge_index buffer is int64

// ---------------- dtype detection for edge_index ----------------
__global__ void k_detect(const int* __restrict__ v) {
    __shared__ int nz[256];
    int t = threadIdx.x;
    nz[t] = v[2 * t + 1];
    __syncthreads();
    for (int s = 128; s > 0; s >>= 1) {
        if (t < s) nz[t] |= nz[t + s];
        __syncthreads();
    }
    if (t == 0) g_is64 = (nz[0] == 0) ? 1 : 0;
}

__global__ void k_zero_pass() {
    int i = blockIdx.x * blockDim.x + threadIdx.x;
    if (i < BB * NN) { g_deg[i] = 0.0f; g_s[i] = 0.0f; }
}

// ---------------- degree / edge-scalar scatter + edge-index repack ----------------
__global__ void k_degs(const void* __restrict__ ei, const float* __restrict__ eattr) {
    int gid = blockIdx.x * blockDim.x + threadIdx.x;
    if (gid >= BB * EE) return;
    int b = gid / EE, e = gid - b * EE;
    int src, dst;
    if (g_is64) {
        const long long* e64 = (const long long*)ei;
        src = (int)e64[(long long)b * 2 * EE + e];
        dst = (int)e64[(long long)b * 2 * EE + EE + e];
    } else {
        const int* e32 = (const int*)ei;
        src = e32[b * 2 * EE + e];
        dst = e32[b * 2 * EE + EE + e];
    }
    src = (src < 0) ? 0 : (src >= NN ? NN - 1 : src);
    dst = (dst < 0) ? 0 : (dst >= NN ? NN - 1 : dst);
    g_ei32[gid] = make_int2(src, dst);
    atomicAdd(&g_deg[b * NN + dst], 1.0f);
    atomicAdd(&g_s[b * NN + dst], eattr[gid]);
}

// ---------------- 3-phase parallel scan for CSR rowptr ----------------
__global__ void k_scan1() {            // grid BB*SCB, 256 threads: block degree sums
    __shared__ int sh[256];
    int blk = blockIdx.x;
    int batch = blk / SCB, loc = blk - batch * SCB;
    int node = loc * 256 + threadIdx.x;
    int d = (node < NN) ? (int)g_deg[batch * NN + node] : 0;
    sh[threadIdx.x] = d;
    __syncthreads();
    for (int s = 128; s > 0; s >>= 1) {
        if (threadIdx.x < s) sh[threadIdx.x] += sh[threadIdx.x + s];
        __syncthreads();
    }
    if (threadIdx.x == 0) g_bsum[blk] = sh[0];
}

__global__ void k_scan2() {            // 1 block: exclusive scan of partials per batch
    __shared__ int sh[BB * SCB];
    int t = threadIdx.x;               // 512
    if (t < BB * SCB) sh[t] = g_bsum[t];
    __syncthreads();
    if (t < BB) {                      // serial scan of 79 values per batch (fast in smem)
        int off = 0;
        for (int i = 0; i < SCB; i++) {
            int v = sh[t * SCB + i];
            sh[t * SCB + i] = off;
            off += v;
        }
    }
    __syncthreads();
    if (t < BB * SCB) g_bsum[t] = sh[t];
}

__global__ void k_scan3() {            // grid BB*SCB, 256: local exclusive scan + base
    __shared__ int sh[256];
    int blk = blockIdx.x;
    int batch = blk / SCB, loc = blk - batch * SCB;
    int node = loc * 256 + threadIdx.x;
    int t = threadIdx.x;
    int d = (node < NN) ? (int)g_deg[batch * NN + node] : 0;
    sh[t] = d;
    __syncthreads();
    for (int off = 1; off < 256; off <<= 1) {
        int y = (t >= off) ? sh[t - off] : 0;
        __syncthreads();
        sh[t] += y;
        __syncthreads();
    }
    if (node < NN) {
        int excl = sh[t] - d + g_bsum[blk];
        g_rowptr[batch * NN + node] = excl;
        g_fill[batch * NN + node] = excl;
    }
}

// ---------------- CSR fill: bucket src ids by dst ----------------
__global__ void k_fill() {
    int gid = blockIdx.x * blockDim.x + threadIdx.x;
    if (gid >= BB * EE) return;
    int b = gid / EE;
    int2 sd = g_ei32[gid];
    int pos = atomicAdd(&g_fill[b * NN + sd.y], 1);
    g_csr[b * EE + pos] = sd.x;
}

// ---------------- input embedding: h = x @ inW + inb ----------------
__global__ void __launch_bounds__(256) k_embed(const float* __restrict__ x,
                                               const float* __restrict__ inW,
                                               const float* __restrict__ inb) {
    __shared__ __align__(16) float Wsh[INDIM * ED];
    __shared__ float xs[16][INDIM];
    int tid = threadIdx.x;                       // 256
    for (int i = tid; i < INDIM * ED; i += 256) Wsh[i] = inW[i];
    int row0 = blockIdx.x * 16;
    for (int i = tid; i < 16 * INDIM; i += 256) {
        int r = i / INDIM, k = i - r * INDIM;
        xs[r][k] = x[(long long)(row0 + r) * INDIM + k];
    }
    __syncthreads();
    int r = tid >> 4;
    int c4 = tid & 15;
    float4 acc = *reinterpret_cast<const float4*>(&inb[c4 * 4]);
#pragma unroll
    for (int k = 0; k < INDIM; k++) {
        float xv = xs[r][k];
        float4 w = *reinterpret_cast<const float4*>(&Wsh[k * ED + c4 * 4]);
        acc.x += xv * w.x; acc.y += xv * w.y; acc.z += xv * w.z; acc.w += xv * w.w;
    }
    *reinterpret_cast<float4*>(&g_H[(long long)(row0 + r) * ED + c4 * 4]) = acc;
}

// ---------------- CSR gather: A1[n] = sum over in-edges of h[src] ----------------
__global__ void __launch_bounds__(256) k_gather() {
    int gw = (blockIdx.x * blockDim.x + threadIdx.x) >> 5;   // global warp = node
    if (gw >= BB * NN) return;
    int b = gw / NN, n = gw - b * NN;
    int lane = threadIdx.x & 31;
    int half = lane >> 4, c4 = lane & 15;
    int start = g_rowptr[b * NN + n];
    int end = start + (int)g_deg[b * NN + n];
    const int* csr = g_csr + b * EE;
    const float* Hb = g_H + (long long)b * NN * ED;
    float4 a0 = make_float4(0.f, 0.f, 0.f, 0.f);
    float4 a1 = make_float4(0.f, 0.f, 0.f, 0.f);
    int e = start + half;
    for (; e + 2 < end; e += 4) {
        int s0 = csr[e];
        int s1 = csr[e + 2];
        float4 v0 = *reinterpret_cast<const float4*>(&Hb[(long long)s0 * ED + c4 * 4]);
        float4 v1 = *reinterpret_cast<const float4*>(&Hb[(long long)s1 * ED + c4 * 4]);
        a0.x += v0.x; a0.y += v0.y; a0.z += v0.z; a0.w += v0.w;
        a1.x += v1.x; a1.y += v1.y; a1.z += v1.z; a1.w += v1.w;
    }
    if (e < end) {
        int s0 = csr[e];
        float4 v0 = *reinterpret_cast<const float4*>(&Hb[(long long)s0 * ED + c4 * 4]);
        a0.x += v0.x; a0.y += v0.y; a0.z += v0.z; a0.w += v0.w;
    }
    a0.x += a1.x; a0.y += a1.y; a0.z += a1.z; a0.w += a1.w;
    a0.x += __shfl_xor_sync(0xffffffffu, a0.x, 16);
    a0.y += __shfl_xor_sync(0xffffffffu, a0.y, 16);
    a0.z += __shfl_xor_sync(0xffffffffu, a0.z, 16);
    a0.w += __shfl_xor_sync(0xffffffffu, a0.w, 16);
    if (half == 0)
        *reinterpret_cast<float4*>(&g_A1[((long long)(b * NN + n)) * ED + c4 * 4]) = a0;
}

// ---------------- all-layer rank-1 terms u,v + zero BN stats (once, upfront) ----------------
__global__ void k_uv_all(const float* __restrict__ edgeW, const float* __restrict__ edgeb,
                         const float* __restrict__ W1) {
    int l = blockIdx.x;    // LL
    int c = threadIdx.x;   // 128
    for (int i = c; i < BB * 2 * H2; i += 128) g_stats[l * BB * 2 * H2 + i] = 0.0f;
    float u = 0.f, v = 0.f;
#pragma unroll
    for (int k = 0; k < ED; k++) {
        float w1 = W1[((long long)l * H2 + ED + k) * H2 + c];
        u += edgeW[l * ED + k] * w1;
        v += edgeb[l * ED + k] * w1;
    }
    g_uv[l * 2 * H2 + c] = u;
    g_uv[l * 2 * H2 + H2 + c] = v;
}

// ---------------- GEMM1: P = A1 @ W1_top + b1 + s*u + deg*v, + BN stats (32 rows/block) ----------------
__global__ void __launch_bounds__(128) k_gemm1(const float* __restrict__ W1,
                                               const float* __restrict__ b1, int l) {
    __shared__ __align__(16) float Wsh[ED * H2];   // 32 KB, [k][c]
    __shared__ __align__(16) float ash[32 * ED];   // 8 KB, 32 rows of A1
    __shared__ float red[4][2 * H2];               // 4 KB
    int tid = threadIdx.x;               // 128
    int b = blockIdx.x;
    int n0 = blockIdx.y * 32;

    for (int i = tid; i < ED * H2; i += 128) Wsh[i] = W1[(long long)l * H2 * H2 + i];
    {
        const float4* A1b = reinterpret_cast<const float4*>(g_A1 + ((long long)(b * NN + n0)) * ED);
        float4* a4 = reinterpret_cast<float4*>(ash);
        for (int i = tid; i < 32 * ED / 4; i += 128) a4[i] = A1b[i];
    }
    __syncthreads();

    int ry = tid >> 5;    // warp id: 4 groups of 8 rows
    int cx = tid & 31;    // 4 consecutive channels per thread

    const float* uvl = g_uv + l * 2 * H2;
    float uc[4], vc[4], b1c[4];
#pragma unroll
    for (int j = 0; j < 4; j++) {
        int c = cx * 4 + j;
        uc[j] = uvl[c];
        vc[j] = uvl[H2 + c];
        b1c[j] = b1[l * H2 + c];
    }
    float acc[8][4];
#pragma unroll
    for (int i = 0; i < 8; i++) {
        int n = n0 + ry * 8 + i;
        float sv = g_s[b * NN + n];
        float dv = g_deg[b * NN + n];
#pragma unroll
        for (int j = 0; j < 4; j++) acc[i][j] = b1c[j] + sv * uc[j] + dv * vc[j];
    }

#pragma unroll 4
    for (int k = 0; k < ED; k++) {
        float4 w = *reinterpret_cast<const float4*>(&Wsh[k * H2 + cx * 4]);
#pragma unroll
        for (int i = 0; i < 8; i++) {
            float a = ash[(ry * 8 + i) * ED + k];
            acc[i][0] += a * w.x; acc[i][1] += a * w.y;
            acc[i][2] += a * w.z; acc[i][3] += a * w.w;
        }
    }

    float sc[4] = {0.f, 0.f, 0.f, 0.f};
    float sq[4] = {0.f, 0.f, 0.f, 0.f};
#pragma unroll
    for (int i = 0; i < 8; i++) {
        int n = n0 + ry * 8 + i;
        float4 o = make_float4(acc[i][0], acc[i][1], acc[i][2], acc[i][3]);
        *reinterpret_cast<float4*>(&g_P[((long long)(b * NN + n)) * H2 + cx * 4]) = o;
#pragma unroll
        for (int j = 0; j < 4; j++) { sc[j] += acc[i][j]; sq[j] += acc[i][j] * acc[i][j]; }
    }
#pragma unroll
    for (int j = 0; j < 4; j++) {
        red[ry][cx * 4 + j] = sc[j];
        red[ry][H2 + cx * 4 + j] = sq[j];
    }
    __syncthreads();
    float* st = g_stats + (l * BB + b) * 2 * H2;
    for (int i = tid; i < 2 * H2; i += 128) {
        float t = red[0][i] + red[1][i] + red[2][i] + red[3][i];
        atomicAdd(&st[i], t);
    }
}

// ---------------- GEMM2: h' = relu(BN(P)) @ W2 + b2, BN coeffs computed in-block ----------------
__global__ void __launch_bounds__(128) k_gemm2(const float* __restrict__ W2,
                                               const float* __restrict__ b2,
                                               const float* __restrict__ gamma,
                                               const float* __restrict__ beta,
                                               float* __restrict__ out, int l, int writeOut) {
    __shared__ __align__(16) float Wsh[H2 * ED];   // 32 KB, [k][c]
    __shared__ __align__(16) float qsh[32 * H2];   // 16 KB, 32 normalized rows
    int tid = threadIdx.x;             // 128
    int b = blockIdx.x;
    int n0 = blockIdx.y * 32;

    for (int i = tid; i < H2 * ED; i += 128) Wsh[i] = W2[(long long)l * H2 * ED + i];

    // BN coefficients for channel tid (from precomputed global stats)
    const float* st = g_stats + (l * BB + b) * 2 * H2;
    float sum = st[tid];
    float sq  = st[H2 + tid];
    float m = sum / (float)NN;
    float var = sq / (float)NN - m * m;
    float rstd = rsqrtf(var + BN_EPS);
    float scl = rstd * gamma[l * H2 + tid];
    float shf = beta[l * H2 + tid] - m * scl;

    const float* Pb = g_P + ((long long)(b * NN + n0)) * H2;
#pragma unroll 4
    for (int r = 0; r < 32; r++) {
        float p = Pb[r * H2 + tid];
        float q = p * scl + shf;
        qsh[r * H2 + tid] = q > 0.f ? q : 0.f;
    }
    __syncthreads();

    int ry = tid >> 4;   // 8 row-groups of 4 rows
    int cx = tid & 15;   // 4 consecutive output channels per thread
    float acc[4][4];
#pragma unroll
    for (int i = 0; i < 4; i++)
#pragma unroll
        for (int j = 0; j < 4; j++) acc[i][j] = b2[l * ED + cx * 4 + j];

#pragma unroll 8
    for (int k = 0; k < H2; k++) {
        float4 w = *reinterpret_cast<const float4*>(&Wsh[k * ED + cx * 4]);
        float a0 = qsh[(ry * 4 + 0) * H2 + k];
        float a1 = qsh[(ry * 4 + 1) * H2 + k];
        float a2 = qsh[(ry * 4 + 2) * H2 + k];
        float a3 = qsh[(ry * 4 + 3) * H2 + k];
        acc[0][0] += a0 * w.x; acc[0][1] += a0 * w.y; acc[0][2] += a0 * w.z; acc[0][3] += a0 * w.w;
        acc[1][0] += a1 * w.x; acc[1][1] += a1 * w.y; acc[1][2] += a1 * w.z; acc[1][3] += a1 * w.w;
        acc[2][0] += a2 * w.x; acc[2][1] += a2 * w.y; acc[2][2] += a2 * w.z; acc[2][3] += a2 * w.w;
        acc[3][0] += a3 * w.x; acc[3][1] += a3 * w.y; acc[3][2] += a3 * w.z; acc[3][3] += a3 * w.w;
    }

#pragma unroll
    for (int i = 0; i < 4; i++) {
        int n = n0 + ry * 4 + i;
        float4 o;
        if (writeOut) {
            o = make_float4(acc[i][0], acc[i][1], acc[i][2], acc[i][3]);
            *reinterpret_cast<float4*>(&out[((long long)(b * NN + n)) * ED + cx * 4]) = o;
        } else {
            o = make_float4(acc[i][0] > 0.f ? acc[i][0] : 0.f,
                            acc[i][1] > 0.f ? acc[i][1] : 0.f,
                            acc[i][2] > 0.f ? acc[i][2] : 0.f,
                            acc[i][3] > 0.f ? acc[i][3] : 0.f);
            *reinterpret_cast<float4*>(&g_H[((long long)(b * NN + n)) * ED + cx * 4]) = o;
        }
    }
}

// ---------------- launcher ----------------
extern "C" void kernel_launch(void* const* d_in, const int* in_sizes, int n_in,
                              void* d_out, int out_size) {
    const float*     x      = (const float*)d_in[0];
    const void*      ei     = (const void*)d_in[1];   // int32 or int64, auto-detected
    const float*     eattr  = (const float*)d_in[2];
    const float*     inW    = (const float*)d_in[3];
    const float*     inb    = (const float*)d_in[4];
    const float*     edgeW  = (const float*)d_in[5];
    const float*     edgeb  = (const float*)d_in[6];
    const float*     W1     = (const float*)d_in[7];
    const float*     b1     = (const float*)d_in[8];
    const float*     gamma  = (const float*)d_in[9];
    const float*     beta   = (const float*)d_in[10];
    const float*     W2     = (const float*)d_in[11];
    const float*     b2     = (const float*)d_in[12];
    float* out = (float*)d_out;

    k_detect<<<1, 256>>>((const int*)ei);
    k_zero_pass<<<(BB * NN + 255) / 256, 256>>>();
    k_uv_all<<<LL, 128>>>(edgeW, edgeb, W1);
    k_degs<<<(BB * EE + 255) / 256, 256>>>(ei, eattr);
    k_scan1<<<BB * SCB, 256>>>();
    k_scan2<<<1, 512>>>();
    k_scan3<<<BB * SCB, 256>>>();
    k_fill<<<(BB * EE + 255) / 256, 256>>>();
    k_embed<<<BB * NN / 16, 256>>>(x, inW, inb);

    for (int l = 0; l < LL; l++) {
        k_gather<<<(BB * NN * 32 + 255) / 256, 256>>>();
        k_gemm1<<<dim3(BB, NN / 32), 128>>>(W1, b1, l);
        k_gemm2<<<dim3(BB, NN / 32), 128>>>(W2, b2, gamma, beta, out, l, (l == LL - 1) ? 1 : 0);
    }
}